// round 1
// baseline (speedup 1.0000x reference)
#include <cuda_runtime.h>
#include <math.h>

// Problem dims (fixed by the reference: [4,1,512,512] f32)
#define IMG_H 512
#define IMG_W 512
#define MAX_B 8
#define MAX_NPIX (MAX_B * IMG_H * IMG_W)

// Scratch: double-buffered u, plus q and w. ~128 MB static, fine.
__device__ float g_u0[MAX_NPIX];
__device__ float g_u1[MAX_NPIX];
__device__ float g_q[MAX_NPIX];
__device__ float g_w[MAX_NPIX];

// ---------------------------------------------------------------------------
// init: u = sigmoid(o); q = clip(v - u, -1, 1); w = (u + v) / 2
// ---------------------------------------------------------------------------
__global__ void __launch_bounds__(256) init_kernel(
    const float* __restrict__ o, const float* __restrict__ v,
    float* __restrict__ u, float* __restrict__ q, float* __restrict__ w, int n)
{
    int i = blockIdx.x * blockDim.x + threadIdx.x;
    if (i >= n) return;
    float ov = o[i];
    float vv = v[i];
    float uu = 1.0f / (1.0f + expf(-ov));
    u[i] = uu;
    q[i] = fminf(fmaxf(vv - uu, -1.0f), 1.0f);
    w[i] = 0.5f * (uu + vv);
}

// ---------------------------------------------------------------------------
// One fused fixed-point iteration:
//   p     = conv5x5(1 - 2*u_in, gauss(sigma=5))   (zero-padded SAME)
//   u_out = sigmoid(o - p + 2*q)
//   q     = clip(q + (w - u_out), -1, 1)
//   if do_wupd: w -= 0.001 * (2 * q_new)          (gradient term dropped; see notes)
//   if do_out:  out = o - p + 2*q_new
// ---------------------------------------------------------------------------
__global__ void __launch_bounds__(256) iter_kernel(
    const float* __restrict__ uin, float* __restrict__ uout,
    const float* __restrict__ o,
    float* __restrict__ q, float* __restrict__ w,
    float* __restrict__ out,
    int do_wupd, int do_out)
{
    // tile: 32x8 outputs, halo 2 -> 36x12 shared
    __shared__ float s[12][36];

    const int b  = blockIdx.z;
    const int x0 = blockIdx.x * 32;
    const int y0 = blockIdx.y * 8;
    const float* up = uin + (size_t)b * IMG_H * IMG_W;

    const int tid = threadIdx.y * 32 + threadIdx.x;
    #pragma unroll
    for (int i = tid; i < 36 * 12; i += 256) {
        int sy = i / 36, sx = i - sy * 36;
        int gx = x0 + sx - 2, gy = y0 + sy - 2;
        float val = 0.0f;  // SAME conv zero-pads the conv INPUT (1-2u) with 0
        if (gx >= 0 && gx < IMG_W && gy >= 0 && gy < IMG_H)
            val = 1.0f - 2.0f * up[gy * IMG_W + gx];
        s[sy][sx] = val;
    }
    __syncthreads();

    // separable gaussian, sigma=5, half-size 2:
    // w1d = exp(-r^2/50), r=-2..2 ; normalized by S^2 (== 2D sum)
    const float W1[5] = {0.923116346f, 0.980198673f, 1.0f, 0.980198673f, 0.923116346f};
    const float S1 = 4.806630039f;
    const float invS2 = 1.0f / (S1 * S1);

    const int tx = threadIdx.x, ty = threadIdx.y;
    float acc = 0.0f;
    #pragma unroll
    for (int dy = 0; dy < 5; dy++) {
        float r = 0.0f;
        #pragma unroll
        for (int dx = 0; dx < 5; dx++)
            r += W1[dx] * s[ty + dy][tx + dx];
        acc += W1[dy] * r;
    }
    const float p = acc * invS2;

    const int x = x0 + tx, y = y0 + ty;
    const size_t idx = (size_t)b * IMG_H * IMG_W + (size_t)y * IMG_W + x;

    const float ov = o[idx];
    const float qv = q[idx];
    const float wv = w[idx];

    const float un = 1.0f / (1.0f + expf(-(ov - p + 2.0f * qv)));
    const float qn = fminf(fmaxf(qv + (wv - un), -1.0f), 1.0f);

    uout[idx] = un;
    q[idx]    = qn;
    if (do_wupd) w[idx] = wv - 0.001f * (2.0f * qn);
    if (do_out)  out[idx] = ov - p + 2.0f * qn;
}

// ---------------------------------------------------------------------------
extern "C" void kernel_launch(void* const* d_in, const int* in_sizes, int n_in,
                              void* d_out, int out_size)
{
    const float* o = (const float*)d_in[0];
    const float* v = (const float*)d_in[1];
    float* out = (float*)d_out;

    const int n = in_sizes[0];
    const int B = n / (IMG_H * IMG_W);

    float *u0, *u1, *q, *w;
    cudaGetSymbolAddress((void**)&u0, g_u0);
    cudaGetSymbolAddress((void**)&u1, g_u1);
    cudaGetSymbolAddress((void**)&q,  g_q);
    cudaGetSymbolAddress((void**)&w,  g_w);

    init_kernel<<<(n + 255) / 256, 256>>>(o, v, u0, q, w, n);

    dim3 blk(32, 8, 1);
    dim3 grd(IMG_W / 32, IMG_H / 8, B);
    for (int i = 0; i < 20; i++) {
        const float* uin = (i & 1) ? u1 : u0;
        float*       uo  = (i & 1) ? u0 : u1;
        iter_kernel<<<grd, blk>>>(uin, uo, o, q, w, out,
                                  (i % 5 == 0) ? 1 : 0,
                                  (i == 19) ? 1 : 0);
    }
}